// round 7
// baseline (speedup 1.0000x reference)
#include <cuda_runtime.h>
#include <cuda_bf16.h>

#define N_NODES 50000
#define EMB 128
#define N_EDGES 600000
#define NLAYER 5
#define BN_EPS 1e-5f

// ---------------- device scratch ----------------
__device__ float g_h[N_NODES * EMB];
__device__ float g_agg[N_NODES * EMB];
__device__ float g_hidden[N_NODES * 2 * EMB];
__device__ float g_h2[N_NODES * EMB];
__device__ float g_sums[2 * EMB];
__device__ float g_scale[EMB];
__device__ float g_shift[EMB];
__device__ int g_counts[N_NODES];
__device__ int g_cursor[N_NODES];
__device__ int g_rowptr[N_NODES + 1];
__device__ unsigned g_elist[N_EDGES];

// ---------------- f32x2 helpers ----------------
__device__ __forceinline__ unsigned long long pack2_dup(float a) {
    unsigned long long r;
    asm("mov.b64 %0, {%1,%1};" : "=l"(r) : "f"(a));
    return r;
}
__device__ __forceinline__ unsigned long long fma2(unsigned long long a,
                                                   unsigned long long b,
                                                   unsigned long long c) {
    unsigned long long d;
    asm("fma.rn.f32x2 %0, %1, %2, %3;" : "=l"(d) : "l"(a), "l"(b), "l"(c));
    return d;
}
__device__ __forceinline__ void unpack2(unsigned long long v, float& lo, float& hi) {
    asm("mov.b64 {%0,%1}, %2;" : "=f"(lo), "=f"(hi) : "l"(v));
}

// ---------------- embedding ----------------
__global__ __launch_bounds__(256)
void embed_kernel(const int* __restrict__ x,
                  const float4* __restrict__ atom,
                  const float4* __restrict__ chir,
                  const float4* __restrict__ hyb,
                  float4* __restrict__ h) {
    int t = blockIdx.x * blockDim.x + threadIdx.x;
    if (t >= N_NODES * 32) return;
    int node = t >> 5, lane = t & 31;
    int a  = x[3 * node + 0];
    int c  = x[3 * node + 1];
    int hy = x[3 * node + 2];
    float4 o  = atom[a * 32 + lane];
    float4 c4 = chir[c * 32 + lane];
    float4 h4 = hyb[hy * 32 + lane];
    o.x += c4.x + h4.x; o.y += c4.y + h4.y;
    o.z += c4.z + h4.z; o.w += c4.w + h4.w;
    h[t] = o;
}

// ---------------- CSR build (once per call) ----------------
__global__ __launch_bounds__(256)
void zero_counts(int* __restrict__ counts, float* __restrict__ sums) {
    int t = blockIdx.x * blockDim.x + threadIdx.x;
    if (t < N_NODES) counts[t] = 0;
    if (t < 2 * EMB) sums[t] = 0.f;
}

__global__ __launch_bounds__(256)
void hist_kernel(const int* __restrict__ ei, int* __restrict__ counts) {
    int e = blockIdx.x * blockDim.x + threadIdx.x;
    if (e < N_EDGES) atomicAdd(&counts[ei[N_EDGES + e]], 1);
}

__global__ __launch_bounds__(1024)
void scan_kernel(const int* __restrict__ counts, int* __restrict__ rowptr,
                 int* __restrict__ cursor) {
    __shared__ int part[1024];
    const int tid = threadIdx.x;
    const int CH = (N_NODES + 1023) / 1024;  // 49
    const int beg = tid * CH;
    int s = 0;
    for (int i = 0; i < CH; i++) {
        int idx = beg + i;
        if (idx < N_NODES) s += counts[idx];
    }
    part[tid] = s;
    __syncthreads();
    for (int off = 1; off < 1024; off <<= 1) {
        int add = (tid >= off) ? part[tid - off] : 0;
        __syncthreads();
        part[tid] += add;
        __syncthreads();
    }
    int run = (tid > 0) ? part[tid - 1] : 0;
    for (int i = 0; i < CH; i++) {
        int idx = beg + i;
        if (idx < N_NODES) {
            int c = counts[idx];
            rowptr[idx] = run;
            cursor[idx] = run;
            run += c;
        }
    }
    if (tid == 1023) rowptr[N_NODES] = part[1023];
}

__global__ __launch_bounds__(256)
void fill_kernel(const int* __restrict__ ei, const int* __restrict__ ea,
                 int* __restrict__ cursor, unsigned* __restrict__ elist) {
    int e = blockIdx.x * blockDim.x + threadIdx.x;
    if (e >= N_EDGES) return;
    int src = ei[e];
    int dst = ei[N_EDGES + e];
    unsigned a0 = (unsigned)ea[2 * e];
    unsigned a1 = (unsigned)ea[2 * e + 1];
    int pos = atomicAdd(&cursor[dst], 1);
    elist[pos] = (unsigned)src | (a0 << 16) | (a1 << 19);
}

// ------- gather aggregation (one warp per node), optional fused BN+ReLU ----
template<bool BN>
__global__ __launch_bounds__(256)
void agg_kernel(const float4* __restrict__ h,
                const int* __restrict__ rowptr,
                const unsigned* __restrict__ elist,
                const float4* __restrict__ e1l,
                const float4* __restrict__ e2l,
                const float4* __restrict__ scale,
                const float4* __restrict__ shift,
                float4* __restrict__ agg) {
    __shared__ float4 sEE[24 * 32];
    int tid = threadIdx.x;
    for (int i = tid; i < 24 * 32; i += 256) {
        int combo = i >> 5, lane = i & 31;
        int a0 = combo >> 2, a1 = combo & 3;
        float4 v1 = e1l[a0 * 32 + lane];
        float4 v2 = e2l[a1 * 32 + lane];
        float4 o;
        o.x = v1.x + v2.x; o.y = v1.y + v2.y;
        o.z = v1.z + v2.z; o.w = v1.w + v2.w;
        sEE[i] = o;
    }
    __syncthreads();

    int t = blockIdx.x * blockDim.x + tid;
    int n = t >> 5, lane = t & 31;
    if (n >= N_NODES) return;

    float4 sc, sh;
    if (BN) { sc = scale[lane]; sh = shift[lane]; }

    int beg = rowptr[n], end = rowptr[n + 1];
    float4 acc = make_float4(0.f, 0.f, 0.f, 0.f);
    for (int e = beg; e < end; e++) {
        unsigned p = elist[e];
        int src = (int)(p & 0xFFFFu);
        int combo = (int)(((p >> 16) & 7u) * 4u + ((p >> 19) & 3u));
        float4 v = h[src * 32 + lane];
        if (BN) {
            v.x = fmaxf(fmaf(v.x, sc.x, sh.x), 0.f);
            v.y = fmaxf(fmaf(v.y, sc.y, sh.y), 0.f);
            v.z = fmaxf(fmaf(v.z, sc.z, sh.z), 0.f);
            v.w = fmaxf(fmaf(v.w, sc.w, sh.w), 0.f);
        }
        float4 ee = sEE[combo * 32 + lane];
        acc.x += v.x + ee.x; acc.y += v.y + ee.y;
        acc.z += v.z + ee.z; acc.w += v.w + ee.w;
    }
    agg[n * 32 + lane] = acc;
}

// ------- f32x2 SGEMM: 128x128 tile, 8x8 microtile, BK=16, double-buffered ---
template<int K, int N, bool RELU, bool STATS>
__global__ __launch_bounds__(256, 2)
void gemm128(const float* __restrict__ A, const float* __restrict__ B,
             const float* __restrict__ bias, float* __restrict__ C,
             int M, float* __restrict__ sums) {
    __shared__ float As[2][16][128];
    __shared__ float Bs[2][16][128];
    __shared__ float sS[128];
    __shared__ float sQ[128];

    const int tid = threadIdx.x;
    const int tx = tid & 15;
    const int ty = tid >> 4;
    const int row0 = blockIdx.x * 128;
    const int col0 = blockIdx.y * 128;

    if (STATS && tid < 128) { sS[tid] = 0.f; sQ[tid] = 0.f; }

    const int ar = tid & 127;
    const int ac = (tid >> 7) * 8;
    const bool arow_ok = (row0 + ar) < M;
    // B load mapping: idx = tid + r*256 -> bk = idx>>5, bc = (idx&31)*4
    const int bk0 = tid >> 5;
    const int bc0 = (tid & 31) * 4;
    const int bk1 = (tid + 256) >> 5;
    const int bc1 = bc0;

    constexpr int NIT = K / 16;

    unsigned long long acc[8][4];
#pragma unroll
    for (int m = 0; m < 8; m++)
#pragma unroll
        for (int n = 0; n < 4; n++) acc[m][n] = 0ull;

    // prologue: tile 0 -> buffer 0
    {
        float4 av0 = make_float4(0.f, 0.f, 0.f, 0.f), av1 = av0;
        if (arow_ok) {
            const float* ap = A + (size_t)(row0 + ar) * K + ac;
            av0 = *(const float4*)ap;
            av1 = *(const float4*)(ap + 4);
        }
        As[0][ac + 0][ar] = av0.x; As[0][ac + 1][ar] = av0.y;
        As[0][ac + 2][ar] = av0.z; As[0][ac + 3][ar] = av0.w;
        As[0][ac + 4][ar] = av1.x; As[0][ac + 5][ar] = av1.y;
        As[0][ac + 6][ar] = av1.z; As[0][ac + 7][ar] = av1.w;
        *(float4*)&Bs[0][bk0][bc0] = *(const float4*)(B + (size_t)bk0 * N + col0 + bc0);
        *(float4*)&Bs[0][bk1][bc1] = *(const float4*)(B + (size_t)bk1 * N + col0 + bc1);
    }
    __syncthreads();

    float4 pa0, pa1, pb0, pb1;
#pragma unroll
    for (int it = 0; it < NIT; it++) {
        const int buf = it & 1;
        const bool has_next = (it + 1 < NIT);
        if (has_next) {
            int k0 = (it + 1) * 16;
            pa0 = make_float4(0.f, 0.f, 0.f, 0.f); pa1 = pa0;
            if (arow_ok) {
                const float* ap = A + (size_t)(row0 + ar) * K + k0 + ac;
                pa0 = *(const float4*)ap;
                pa1 = *(const float4*)(ap + 4);
            }
            pb0 = *(const float4*)(B + (size_t)(k0 + bk0) * N + col0 + bc0);
            pb1 = *(const float4*)(B + (size_t)(k0 + bk1) * N + col0 + bc1);
        }

#pragma unroll
        for (int k = 0; k < 16; k++) {
            float4 a0 = *(const float4*)&As[buf][k][ty * 8];
            float4 a1 = *(const float4*)&As[buf][k][ty * 8 + 4];
            const unsigned long long* bp = (const unsigned long long*)&Bs[buf][k][tx * 8];
            unsigned long long b0 = bp[0], b1 = bp[1], b2 = bp[2], b3 = bp[3];
            float av[8] = {a0.x, a0.y, a0.z, a0.w, a1.x, a1.y, a1.z, a1.w};
#pragma unroll
            for (int m = 0; m < 8; m++) {
                unsigned long long am = pack2_dup(av[m]);
                acc[m][0] = fma2(am, b0, acc[m][0]);
                acc[m][1] = fma2(am, b1, acc[m][1]);
                acc[m][2] = fma2(am, b2, acc[m][2]);
                acc[m][3] = fma2(am, b3, acc[m][3]);
            }
        }

        if (has_next) {
            const int nb = buf ^ 1;
            As[nb][ac + 0][ar] = pa0.x; As[nb][ac + 1][ar] = pa0.y;
            As[nb][ac + 2][ar] = pa0.z; As[nb][ac + 3][ar] = pa0.w;
            As[nb][ac + 4][ar] = pa1.x; As[nb][ac + 5][ar] = pa1.y;
            As[nb][ac + 6][ar] = pa1.z; As[nb][ac + 7][ar] = pa1.w;
            *(float4*)&Bs[nb][bk0][bc0] = pb0;
            *(float4*)&Bs[nb][bk1][bc1] = pb1;
            __syncthreads();
        }
    }

    // epilogue
    float bv[8];
#pragma unroll
    for (int n = 0; n < 8; n++) bv[n] = bias[col0 + tx * 8 + n];

    float colS[8] = {}, colQ[8] = {};
#pragma unroll
    for (int m = 0; m < 8; m++) {
        int r = row0 + ty * 8 + m;
        float c[8];
#pragma unroll
        for (int n = 0; n < 4; n++) unpack2(acc[m][n], c[2 * n], c[2 * n + 1]);
        if (r < M) {
#pragma unroll
            for (int n = 0; n < 8; n++) {
                c[n] += bv[n];
                if (RELU) c[n] = fmaxf(c[n], 0.f);
                if (STATS) { colS[n] += c[n]; colQ[n] += c[n] * c[n]; }
            }
            float* cp = C + (size_t)r * N + col0 + tx * 8;
            *(float4*)cp       = make_float4(c[0], c[1], c[2], c[3]);
            *(float4*)(cp + 4) = make_float4(c[4], c[5], c[6], c[7]);
        }
    }

    if (STATS) {
#pragma unroll
        for (int n = 0; n < 8; n++) {
            atomicAdd(&sS[tx * 8 + n], colS[n]);
            atomicAdd(&sQ[tx * 8 + n], colQ[n]);
        }
        __syncthreads();
        if (tid < 128) {
            atomicAdd(&sums[col0 + tid], sS[tid]);
            atomicAdd(&sums[EMB + col0 + tid], sQ[tid]);
        }
    }
}

// ---------------- BN prep (also resets sums for next layer) ----------------
__global__ void bn_prep(float* __restrict__ sums,
                        const float* __restrict__ gamma,
                        const float* __restrict__ beta,
                        float* __restrict__ scale,
                        float* __restrict__ shift) {
    int c = threadIdx.x;
    if (c >= EMB) return;
    const float inv_n = 1.0f / (float)N_NODES;
    float mu  = sums[c] * inv_n;
    float var = sums[EMB + c] * inv_n - mu * mu;
    float rs  = rsqrtf(var + BN_EPS);
    float sc  = gamma[c] * rs;
    scale[c] = sc;
    shift[c] = beta[c] - mu * sc;
    sums[c] = 0.f;
    sums[EMB + c] = 0.f;
}

// final output: out = h2 * scale + shift (no relu)
__global__ __launch_bounds__(256)
void bn_apply(const float4* __restrict__ h2, float4* __restrict__ out,
              const float4* __restrict__ scale, const float4* __restrict__ shift) {
    int t = blockIdx.x * blockDim.x + threadIdx.x;
    if (t >= N_NODES * 32) return;
    int lane = t & 31;
    float4 v  = h2[t];
    float4 sc = scale[lane];
    float4 sh = shift[lane];
    float4 o;
    o.x = fmaf(v.x, sc.x, sh.x);
    o.y = fmaf(v.y, sc.y, sh.y);
    o.z = fmaf(v.z, sc.z, sh.z);
    o.w = fmaf(v.w, sc.w, sh.w);
    out[t] = o;
}

// ---------------- launch ----------------
extern "C" void kernel_launch(void* const* d_in, const int* in_sizes, int n_in,
                              void* d_out, int out_size) {
    const int*   x    = (const int*)  d_in[0];
    const int*   ei   = (const int*)  d_in[1];
    const int*   ea   = (const int*)  d_in[2];
    const float* atom = (const float*)d_in[3];
    const float* chir = (const float*)d_in[4];
    const float* hyb  = (const float*)d_in[5];
    const float* e1   = (const float*)d_in[6];
    const float* e2   = (const float*)d_in[7];
    const float* W1   = (const float*)d_in[8];
    const float* b1   = (const float*)d_in[9];
    const float* W2   = (const float*)d_in[10];
    const float* b2   = (const float*)d_in[11];
    const float* gamma= (const float*)d_in[12];
    const float* beta = (const float*)d_in[13];
    float* out = (float*)d_out;

    float *h, *agg, *hidden, *h2, *sums, *scale, *shift;
    int *counts, *cursor, *rowptr;
    unsigned* elist;
    cudaGetSymbolAddress((void**)&h,      g_h);
    cudaGetSymbolAddress((void**)&agg,    g_agg);
    cudaGetSymbolAddress((void**)&hidden, g_hidden);
    cudaGetSymbolAddress((void**)&h2,     g_h2);
    cudaGetSymbolAddress((void**)&sums,   g_sums);
    cudaGetSymbolAddress((void**)&scale,  g_scale);
    cudaGetSymbolAddress((void**)&shift,  g_shift);
    cudaGetSymbolAddress((void**)&counts, g_counts);
    cudaGetSymbolAddress((void**)&cursor, g_cursor);
    cudaGetSymbolAddress((void**)&rowptr, g_rowptr);
    cudaGetSymbolAddress((void**)&elist,  g_elist);

    const int tpb = 256;
    const int node_grid = (N_NODES * 32) / tpb;
    const int edge_grid = (N_EDGES + tpb - 1) / tpb;
    const int cnt_grid  = (N_NODES + tpb - 1) / tpb;
    const dim3 g1((N_NODES + 127) / 128, 2);
    const dim3 g2((N_NODES + 127) / 128, 1);

    zero_counts<<<cnt_grid, tpb>>>(counts, sums);
    hist_kernel<<<edge_grid, tpb>>>(ei, counts);
    scan_kernel<<<1, 1024>>>(counts, rowptr, cursor);
    fill_kernel<<<edge_grid, tpb>>>(ei, ea, cursor, elist);

    embed_kernel<<<node_grid, tpb>>>(x, (const float4*)atom, (const float4*)chir,
                                     (const float4*)hyb, (float4*)h);

    for (int l = 0; l < NLAYER; l++) {
        const float4* e1l = (const float4*)(e1 + (size_t)l * 6 * EMB);
        const float4* e2l = (const float4*)(e2 + (size_t)l * 4 * EMB);
        if (l == 0)
            agg_kernel<false><<<node_grid, tpb>>>((const float4*)h, rowptr, elist,
                                                  e1l, e2l, nullptr, nullptr,
                                                  (float4*)agg);
        else
            agg_kernel<true><<<node_grid, tpb>>>((const float4*)h2, rowptr, elist,
                                                 e1l, e2l, (const float4*)scale,
                                                 (const float4*)shift, (float4*)agg);
        gemm128<128, 256, true,  false><<<g1, tpb>>>(agg, W1 + (size_t)l * 128 * 256,
                                                     b1 + (size_t)l * 256, hidden,
                                                     N_NODES, nullptr);
        gemm128<256, 128, false, true ><<<g2, tpb>>>(hidden, W2 + (size_t)l * 256 * 128,
                                                     b2 + (size_t)l * 128, h2,
                                                     N_NODES, sums);
        bn_prep<<<1, 128>>>(sums, gamma + (size_t)l * EMB, beta + (size_t)l * EMB,
                            scale, shift);
    }
    bn_apply<<<node_grid, tpb>>>((const float4*)h2, (float4*)out,
                                 (const float4*)scale, (const float4*)shift);
}